// round 11
// baseline (speedup 1.0000x reference)
#include <cuda_runtime.h>

// ---------------------------------------------------------------------------
// SimpleRNN: 2-layer bidirectional tanh RNN + FC head.  B=32,T=2048,H=512.
//  - recurrence: Whh register-resident (128 regs/thread), fma.f32x2 along k,
//    ONE phase per step (4 batch chains), h broadcast via plain
//    st.shared::cluster, sync via split barrier.cluster.arrive/wait.
//  - GEMMs: R3 measured-best (BM128/BN64/BK16, f32x2 packed along M).
// ---------------------------------------------------------------------------

#define B_   32
#define T_   2048
#define H_   512
#define V_   8192
#define BT_  (B_ * T_)     // 65536
#define NW_  1024          // 2*H

__device__ float g_WihT[2 * V_ * H_];     //  33.5 MB
__device__ float g_pre [67108864];        // 268 MB  [BT][1024]
__device__ float g_hcat[67108864];        // 268 MB  [BT][1024]

// ---------------------------------------------------------------------------
// 1) Transpose Wih0 [2][H][V] -> g_WihT [2][V][H]
// ---------------------------------------------------------------------------
__global__ void transpose_k(const float* __restrict__ Wih0)
{
    __shared__ float tile[32][33];
    int d  = blockIdx.z;
    const float* S = Wih0   + (size_t)d * H_ * V_;
    float*       D = g_WihT + (size_t)d * V_ * H_;
    int v0 = blockIdx.x * 32;
    int h0 = blockIdx.y * 32;
    int tx = threadIdx.x, ty = threadIdx.y;
#pragma unroll
    for (int i = 0; i < 4; i++)
        tile[ty + 8 * i][tx] = S[(size_t)(h0 + ty + 8 * i) * V_ + v0 + tx];
    __syncthreads();
#pragma unroll
    for (int i = 0; i < 4; i++)
        D[(size_t)(v0 + ty + 8 * i) * H_ + h0 + tx] = tile[tx][ty + 8 * i];
}

// ---------------------------------------------------------------------------
// 2) Gather + biases -> g_pre
// ---------------------------------------------------------------------------
__global__ void gather_k(const int* __restrict__ x,
                         const float* __restrict__ bih0,
                         const float* __restrict__ bhh0)
{
    int bt  = blockIdx.x;
    int idx = __ldg(&x[bt]);
    int o   = threadIdx.x * 4;
    int dir = o >> 9;
    int h   = o & 511;
    float4 w  = *(const float4*)&g_WihT[((size_t)dir * V_ + idx) * H_ + h];
    float4 b1 = *(const float4*)&bih0[o];
    float4 b2 = *(const float4*)&bhh0[o];
    float4 r;
    r.x = w.x + b1.x + b2.x;
    r.y = w.y + b1.y + b2.y;
    r.z = w.z + b1.z + b2.z;
    r.w = w.w + b1.w + b2.w;
    *(float4*)&g_pre[(size_t)bt * NW_ + o] = r;
}

// ---------------------------------------------------------------------------
// dummy: keeps rnn_layer_k at the ncu-profiled ordinal
// ---------------------------------------------------------------------------
__global__ void dummy_k() {}

// ---------------------------------------------------------------------------
// 3/5) Recurrence. 16 clusters x 8 CTAs. CTA rank owns 64 Whh rows in REGS.
// ONE phase per step: thread (kq=tid&3, r=tid>>2) holds w[grow][kq*128..+128)
// in 64 u64 regs, computes 4 batch partial dots, quad shuffle-reduce, lane kq
// keeps batch kq, stores its value into all 8 CTAs' next h-buffer with plain
// st.shared::cluster, then split barrier.cluster.arrive / wait.
// h-buffer per buf: [k-chunk 0..3][4 batch][128], chunk stride 520 floats
// (banks 0/8/16/24 across the quad -> conflict-free broadcast LDS.128).
// ---------------------------------------------------------------------------
#define FMA2(d, a, b) \
    asm("fma.rn.f32x2 %0, %1, %2, %0;" : "+l"(d) : "l"(a), "l"(b))

#define HBUF_FLOATS 2080   // 4 chunks * 520

__global__ void __cluster_dims__(8, 1, 1) __launch_bounds__(256, 1)
rnn_layer_k(const float* __restrict__ Whh)
{
    __shared__ __align__(16) float s_h[2 * HBUF_FLOATS];   // 16.6 KB

    int tid  = threadIdx.x;
    int rank = blockIdx.x & 7;
    int cid  = blockIdx.x >> 3;
    int dir  = cid >> 3;
    int b0   = (cid & 7) * 4;

    int kq   = tid & 3;                  // k-quarter / batch lane
    int r    = tid >> 2;                 // 0..63
    int grow = rank * 64 + r;
    int colbase = dir * H_ + grow;

    // --- my 128-float Whh chunk in registers (64 packed u64) ---
    unsigned long long wp[64];
    const unsigned long long* Wrow = (const unsigned long long*)
        (Whh + ((size_t)dir * H_ + grow) * H_ + kq * 128);
#pragma unroll
    for (int i = 0; i < 64; i++) wp[i] = Wrow[i];

    // --- zero h buffers ---
    for (int i = tid; i < 2 * HBUF_FLOATS; i += 256) s_h[i] = 0.0f;
    __syncthreads();
    asm volatile("barrier.cluster.arrive.aligned;" ::: "memory");
    asm volatile("barrier.cluster.wait.aligned;" ::: "memory");

    unsigned int hbase = (unsigned int)__cvta_generic_to_shared(&s_h[0]);
    unsigned int peer[8];
#pragma unroll
    for (int p = 0; p < 8; p++)
        asm volatile("mapa.shared::cluster.u32 %0, %1, %2;"
                     : "=r"(peer[p]) : "r"(hbase), "r"(p));

    // my write slot inside one h-buffer (bytes):
    // chunk = grow>>7, batch = kq, elem = grow&127
    unsigned int slot = (unsigned)(((grow >> 7) * 520 + kq * 128 + (grow & 127)) * 4);

    size_t batch = (size_t)(b0 + kq);
    float pv = __ldg(&g_pre[((batch * T_ + (dir ? (T_ - 1) : 0)) << 10) + colbase]);

    for (int t = 0; t < T_; t++) {
        int cur = t & 1;
        int nxt = cur ^ 1;

        // 1) partial dots from buf[cur]: my k-chunk, 4 batches
        const ulonglong2* hp = (const ulonglong2*)&s_h[cur * HBUF_FLOATS + kq * 520];
        unsigned long long a0 = 0ULL, a1 = 0ULL, a2 = 0ULL, a3 = 0ULL;
#pragma unroll
        for (int j = 0; j < 32; j++) {
            ulonglong2 h0 = hp[j];
            ulonglong2 h1 = hp[32 + j];
            ulonglong2 h2 = hp[64 + j];
            ulonglong2 h3 = hp[96 + j];
            FMA2(a0, wp[2 * j], h0.x); FMA2(a0, wp[2 * j + 1], h0.y);
            FMA2(a1, wp[2 * j], h1.x); FMA2(a1, wp[2 * j + 1], h1.y);
            FMA2(a2, wp[2 * j], h2.x); FMA2(a2, wp[2 * j + 1], h2.y);
            FMA2(a3, wp[2 * j], h3.x); FMA2(a3, wp[2 * j + 1], h3.y);
        }
        float s0, s1, s2, s3;
        {
            float lo, hi;
            asm("mov.b64 {%0, %1}, %2;" : "=f"(lo), "=f"(hi) : "l"(a0)); s0 = lo + hi;
            asm("mov.b64 {%0, %1}, %2;" : "=f"(lo), "=f"(hi) : "l"(a1)); s1 = lo + hi;
            asm("mov.b64 {%0, %1}, %2;" : "=f"(lo), "=f"(hi) : "l"(a2)); s2 = lo + hi;
            asm("mov.b64 {%0, %1}, %2;" : "=f"(lo), "=f"(hi) : "l"(a3)); s3 = lo + hi;
        }
        // 2) reduce across the 4 kq lanes (lane bits 0-1)
        s0 += __shfl_xor_sync(0xffffffffu, s0, 1);
        s1 += __shfl_xor_sync(0xffffffffu, s1, 1);
        s2 += __shfl_xor_sync(0xffffffffu, s2, 1);
        s3 += __shfl_xor_sync(0xffffffffu, s3, 1);
        s0 += __shfl_xor_sync(0xffffffffu, s0, 2);
        s1 += __shfl_xor_sync(0xffffffffu, s1, 2);
        s2 += __shfl_xor_sync(0xffffffffu, s2, 2);
        s3 += __shfl_xor_sync(0xffffffffu, s3, 2);
        float sel = (kq & 2) ? ((kq & 1) ? s3 : s2) : ((kq & 1) ? s1 : s0);
        float hn  = tanhf(pv + sel);

        if (t < T_ - 1) {
            // 3) broadcast my value to all 8 CTAs' buf[nxt] (fire-and-forget)
            unsigned int off = (unsigned)(nxt * HBUF_FLOATS * 4) + slot;
#pragma unroll
            for (int p = 0; p < 8; p++)
                asm volatile("st.shared::cluster.f32 [%0], %1;"
                             :: "r"(peer[p] + off), "f"(hn) : "memory");
            // 4) release: prior reads done, stores ordered
            asm volatile("barrier.cluster.arrive.aligned;" ::: "memory");
        }

        // 5) off-critical-path work between arrive and wait
        int tt = dir ? (T_ - 1 - t) : t;
        g_hcat[((batch * T_ + tt) << 10) + colbase] = hn;
        if (t < T_ - 1) {
            int tn = dir ? (T_ - 2 - t) : (t + 1);
            pv = __ldg(&g_pre[((batch * T_ + tn) << 10) + colbase]);
            // 6) acquire: all peers' stores to buf[nxt] visible
            asm volatile("barrier.cluster.wait.aligned;" ::: "memory");
        }
    }
    asm volatile("barrier.cluster.arrive.aligned;" ::: "memory");
    asm volatile("barrier.cluster.wait.aligned;" ::: "memory");
}

// ---------------------------------------------------------------------------
// 4/6) C[m][n] = sum_k g_hcat[m][k] * Bw[n][k] + bias1[n] (+ bias2[n])
// M=65536, N=1024, K=1024. BM=128, BN=64, BK=16, 256 thr, 8x4 microtile,
// f32x2 packed along M.  (R3 measured-best version, verbatim.)
// ---------------------------------------------------------------------------
__global__ __launch_bounds__(256)
void gemm_k(const float* __restrict__ Bw,
            const float* __restrict__ bias1,
            const float* __restrict__ bias2,
            float* __restrict__ Cext,
            int use_pre)
{
    __shared__ float As[16 * 130];   // [k][m]
    __shared__ float Bs[16 * 68];    // [k][n]

    float* C = use_pre ? g_pre : Cext;
    const int K = 1024;
    int m0 = blockIdx.y * 128;
    int n0 = blockIdx.x * 64;
    int tid = threadIdx.x;
    int tx = tid & 15;               // n-group: cols n0 + tx*4 .. +4
    int ty = tid >> 4;               // m-group: rows m0 + ty*8 .. +8

    unsigned long long acc[4][4];    // [m-pair][n] packed f32x2
#pragma unroll
    for (int i = 0; i < 4; i++)
#pragma unroll
        for (int j = 0; j < 4; j++) acc[i][j] = 0ULL;

    for (int kt = 0; kt < K; kt += 16) {
#pragma unroll
        for (int i = 0; i < 2; i++) {
            int j  = tid + 256 * i;
            int m  = j >> 2, kq = j & 3;
            float4 v = *(const float4*)&g_hcat[(size_t)(m0 + m) * 1024 + kt + kq * 4];
            As[(kq * 4 + 0) * 130 + m] = v.x;
            As[(kq * 4 + 1) * 130 + m] = v.y;
            As[(kq * 4 + 2) * 130 + m] = v.z;
            As[(kq * 4 + 3) * 130 + m] = v.w;
        }
        {
            int n = tid >> 2, kq = tid & 3;
            float4 v = *(const float4*)&Bw[(size_t)(n0 + n) * 1024 + kt + kq * 4];
            Bs[(kq * 4 + 0) * 68 + n] = v.x;
            Bs[(kq * 4 + 1) * 68 + n] = v.y;
            Bs[(kq * 4 + 2) * 68 + n] = v.z;
            Bs[(kq * 4 + 3) * 68 + n] = v.w;
        }
        __syncthreads();

#pragma unroll
        for (int k = 0; k < 16; k++) {
            const unsigned long long* ap =
                (const unsigned long long*)(As + k * 130 + ty * 8);
            unsigned long long a[4];
            a[0] = ap[0]; a[1] = ap[1]; a[2] = ap[2]; a[3] = ap[3];
            float4 bv = *(const float4*)(Bs + k * 68 + tx * 4);
            unsigned long long b[4];
            asm("mov.b64 %0, {%1, %1};" : "=l"(b[0]) : "f"(bv.x));
            asm("mov.b64 %0, {%1, %1};" : "=l"(b[1]) : "f"(bv.y));
            asm("mov.b64 %0, {%1, %1};" : "=l"(b[2]) : "f"(bv.z));
            asm("mov.b64 %0, {%1, %1};" : "=l"(b[3]) : "f"(bv.w));
#pragma unroll
            for (int i = 0; i < 4; i++)
#pragma unroll
                for (int j = 0; j < 4; j++)
                    FMA2(acc[i][j], a[i], b[j]);
        }
        __syncthreads();
    }

    float bs[4];
#pragma unroll
    for (int j = 0; j < 4; j++) {
        int n = n0 + tx * 4 + j;
        bs[j] = bias1[n] + (bias2 ? bias2[n] : 0.0f);
    }
#pragma unroll
    for (int i = 0; i < 4; i++) {
        float lo[4], hi[4];
#pragma unroll
        for (int j = 0; j < 4; j++) {
            float l, h;
            asm("mov.b64 {%0, %1}, %2;" : "=f"(l), "=f"(h) : "l"(acc[i][j]));
            lo[j] = l; hi[j] = h;
        }
        int mA = m0 + ty * 8 + 2 * i;
        float4 r0, r1;
        r0.x = lo[0] + bs[0]; r0.y = lo[1] + bs[1];
        r0.z = lo[2] + bs[2]; r0.w = lo[3] + bs[3];
        r1.x = hi[0] + bs[0]; r1.y = hi[1] + bs[1];
        r1.z = hi[2] + bs[2]; r1.w = hi[3] + bs[3];
        *(float4*)&C[(size_t)mA * 1024 + n0 + tx * 4]       = r0;
        *(float4*)&C[(size_t)(mA + 1) * 1024 + n0 + tx * 4] = r1;
    }
}

// ---------------------------------------------------------------------------
extern "C" void kernel_launch(void* const* d_in, const int* in_sizes, int n_in,
                              void* d_out, int out_size)
{
    const int*   x    = (const int*)  d_in[0];
    const float* Wih0 = (const float*)d_in[1];
    const float* Whh0 = (const float*)d_in[2];
    const float* bih0 = (const float*)d_in[3];
    const float* bhh0 = (const float*)d_in[4];
    const float* Wih1 = (const float*)d_in[5];
    const float* Whh1 = (const float*)d_in[6];
    const float* bih1 = (const float*)d_in[7];
    const float* bhh1 = (const float*)d_in[8];
    const float* fcW  = (const float*)d_in[9];
    const float* fcb  = (const float*)d_in[10];
    float* out = (float*)d_out;

    transpose_k<<<dim3(V_ / 32, H_ / 32, 2), dim3(32, 8)>>>(Wih0);      // #1
    gather_k<<<BT_, 256>>>(x, bih0, bhh0);                              // #2
    dummy_k<<<1, 32>>>();                                               // #3
    rnn_layer_k<<<128, 256>>>(Whh0);                                    // #4 <- ncu
    gemm_k<<<dim3(16, BT_ / 128), 256>>>(Wih1, bih1, bhh1, nullptr, 1); // #5
    rnn_layer_k<<<128, 256>>>(Whh1);                                    // #6
    gemm_k<<<dim3(16, BT_ / 128), 256>>>(fcW, fcb, nullptr, out, 0);    // #7
}

// round 12
// speedup vs baseline: 1.4798x; 1.4798x over previous
#include <cuda_runtime.h>

// ---------------------------------------------------------------------------
// SimpleRNN: 2-layer bidirectional tanh RNN + FC head.  B=32,T=2048,H=512.
//  - recurrence: Whh register-resident (128 regs/thread), fma.f32x2 along k.
//    NO clusters: groups of 8 plain CTAs exchange h through L2 (st.cg data,
//    red.release.gpu counter, ld.acquire.gpu poll, ld.cg data). Counters are
//    double-banked per layer and cross-reset for graph-replay safety.
//  - GEMMs: R3 measured-best (BM128/BN64/BK16, f32x2 packed along M).
// ---------------------------------------------------------------------------

#define B_   32
#define T_   2048
#define H_   512
#define V_   8192
#define BT_  (B_ * T_)     // 65536
#define NW_  1024          // 2*H

__device__ float g_WihT[2 * V_ * H_];     //  33.5 MB
__device__ float g_pre [67108864];        // 268 MB  [BT][1024]
__device__ float g_hcat[67108864];        // 268 MB  [BT][1024]
__device__ float g_hx  [16 * 2 * 2048];   // [group][buf][4 batch][512]
__device__ unsigned g_cnt[2][16 * 32];    // [layer][group*32] (128B apart)

// ---------------------------------------------------------------------------
// 1) Transpose Wih0 [2][H][V] -> g_WihT [2][V][H]
// ---------------------------------------------------------------------------
__global__ void transpose_k(const float* __restrict__ Wih0)
{
    __shared__ float tile[32][33];
    int d  = blockIdx.z;
    const float* S = Wih0   + (size_t)d * H_ * V_;
    float*       D = g_WihT + (size_t)d * V_ * H_;
    int v0 = blockIdx.x * 32;
    int h0 = blockIdx.y * 32;
    int tx = threadIdx.x, ty = threadIdx.y;
#pragma unroll
    for (int i = 0; i < 4; i++)
        tile[ty + 8 * i][tx] = S[(size_t)(h0 + ty + 8 * i) * V_ + v0 + tx];
    __syncthreads();
#pragma unroll
    for (int i = 0; i < 4; i++)
        D[(size_t)(v0 + ty + 8 * i) * H_ + h0 + tx] = tile[tx][ty + 8 * i];
}

// ---------------------------------------------------------------------------
// 2) Gather + biases -> g_pre
// ---------------------------------------------------------------------------
__global__ void gather_k(const int* __restrict__ x,
                         const float* __restrict__ bih0,
                         const float* __restrict__ bhh0)
{
    int bt  = blockIdx.x;
    int idx = __ldg(&x[bt]);
    int o   = threadIdx.x * 4;
    int dir = o >> 9;
    int h   = o & 511;
    float4 w  = *(const float4*)&g_WihT[((size_t)dir * V_ + idx) * H_ + h];
    float4 b1 = *(const float4*)&bih0[o];
    float4 b2 = *(const float4*)&bhh0[o];
    float4 r;
    r.x = w.x + b1.x + b2.x;
    r.y = w.y + b1.y + b2.y;
    r.z = w.z + b1.z + b2.z;
    r.w = w.w + b1.w + b2.w;
    *(float4*)&g_pre[(size_t)bt * NW_ + o] = r;
}

// ---------------------------------------------------------------------------
// dummy: keeps rnn_layer_k at the ncu-profiled ordinal
// ---------------------------------------------------------------------------
__global__ void dummy_k() {}

// ---------------------------------------------------------------------------
// 3/5) Recurrence via L2 exchange. 16 groups x 8 plain CTAs (grid 128, all
// resident). Thread (kq=tid&3, r=tid>>2) holds w[grow][kq*128..+128) in 64
// u64 regs, computes 4 batch partial dots, quad shuffle-reduce, keeps batch
// kq. Publish: st.cg h -> g_hx[group][t&1], syncthreads, tid0 red.release
// counter += 1. Consume: tid0 polls ld.acquire C >= 8t, syncthreads, all
// threads ld.cg 8KB -> STS (chunk stride 520, conflict-free broadcasts).
// Buffer-reuse safety: C >= 8t  =>  all peers published h_{t-1}  =>  all
// finished reading h_{t-2}  =>  buf[t&1] overwritable at step t.
// ---------------------------------------------------------------------------
#define FMA2(d, a, b) \
    asm("fma.rn.f32x2 %0, %1, %2, %0;" : "+l"(d) : "l"(a), "l"(b))

__global__ void __launch_bounds__(256, 1)
rnn_layer_k(const float* __restrict__ Whh, int layer)
{
    __shared__ __align__(16) float s_h[2080];   // [4 chunks x 520]

    int tid  = threadIdx.x;
    int rank = blockIdx.x & 7;
    int cid  = blockIdx.x >> 3;          // group 0..15
    int dir  = cid >> 3;
    int b0   = (cid & 7) * 4;

    int kq   = tid & 3;                  // k-quarter / batch lane
    int r    = tid >> 2;                 // 0..63
    int grow = rank * 64 + r;
    int colbase = dir * H_ + grow;

    unsigned* Cp = &g_cnt[layer][cid * 32];
    if (tid == 0) g_cnt[layer ^ 1][cid * 32] = 0;   // reset other layer's counter
                                                    // (prev launch done, next not started)

    // --- my 128-float Whh chunk in registers (64 packed u64) ---
    unsigned long long wp[64];
    const unsigned long long* Wrow = (const unsigned long long*)
        (Whh + ((size_t)dir * H_ + grow) * H_ + kq * 128);
#pragma unroll
    for (int i = 0; i < 64; i++) wp[i] = Wrow[i];

    float* hx = g_hx + cid * 2 * 2048;   // this group's two h buffers

    // loader mapping: thread handles 8 consecutive floats of the 2048 buffer
    int lb   = tid >> 6;                 // batch
    int lrow = (tid * 8) & 511;          // row
    int lw   = (lrow >> 7) * 520 + lb * 128 + (lrow & 127);

    size_t batch = (size_t)(b0 + kq);
    float pv = __ldg(&g_pre[((batch * T_ + (dir ? (T_ - 1) : 0)) << 10) + colbase]);

    for (int t = 0; t < T_; t++) {
        float sel = 0.0f;
        if (t > 0) {
            // 1) wait for all 8 CTAs to have published h_{t-1}
            if (tid == 0) {
                unsigned tgt = 8u * (unsigned)t, c;
                do {
                    asm volatile("ld.acquire.gpu.global.u32 %0, [%1];"
                                 : "=r"(c) : "l"(Cp) : "memory");
                } while (c < tgt);
            }
            __syncthreads();

            // 2) pull 8KB h_{t-1} from L2 into smem
            const float4* src = (const float4*)(hx + ((t - 1) & 1) * 2048);
            float4 v0 = __ldcg(src + tid * 2);
            float4 v1 = __ldcg(src + tid * 2 + 1);
            *(float4*)&s_h[lw]     = v0;
            *(float4*)&s_h[lw + 4] = v1;
            __syncthreads();

            // 3) partial dots: my k-chunk, 4 batches
            const ulonglong2* hp = (const ulonglong2*)&s_h[kq * 520];
            unsigned long long a0 = 0ULL, a1 = 0ULL, a2 = 0ULL, a3 = 0ULL;
#pragma unroll
            for (int j = 0; j < 32; j++) {
                ulonglong2 h0 = hp[j];
                ulonglong2 h1 = hp[32 + j];
                ulonglong2 h2 = hp[64 + j];
                ulonglong2 h3 = hp[96 + j];
                FMA2(a0, wp[2 * j], h0.x); FMA2(a0, wp[2 * j + 1], h0.y);
                FMA2(a1, wp[2 * j], h1.x); FMA2(a1, wp[2 * j + 1], h1.y);
                FMA2(a2, wp[2 * j], h2.x); FMA2(a2, wp[2 * j + 1], h2.y);
                FMA2(a3, wp[2 * j], h3.x); FMA2(a3, wp[2 * j + 1], h3.y);
            }
            float s0, s1, s2, s3;
            {
                float lo, hi;
                asm("mov.b64 {%0, %1}, %2;" : "=f"(lo), "=f"(hi) : "l"(a0)); s0 = lo + hi;
                asm("mov.b64 {%0, %1}, %2;" : "=f"(lo), "=f"(hi) : "l"(a1)); s1 = lo + hi;
                asm("mov.b64 {%0, %1}, %2;" : "=f"(lo), "=f"(hi) : "l"(a2)); s2 = lo + hi;
                asm("mov.b64 {%0, %1}, %2;" : "=f"(lo), "=f"(hi) : "l"(a3)); s3 = lo + hi;
            }
            s0 += __shfl_xor_sync(0xffffffffu, s0, 1);
            s1 += __shfl_xor_sync(0xffffffffu, s1, 1);
            s2 += __shfl_xor_sync(0xffffffffu, s2, 1);
            s3 += __shfl_xor_sync(0xffffffffu, s3, 1);
            s0 += __shfl_xor_sync(0xffffffffu, s0, 2);
            s1 += __shfl_xor_sync(0xffffffffu, s1, 2);
            s2 += __shfl_xor_sync(0xffffffffu, s2, 2);
            s3 += __shfl_xor_sync(0xffffffffu, s3, 2);
            sel = (kq & 2) ? ((kq & 1) ? s3 : s2) : ((kq & 1) ? s1 : s0);
        }
        float hn = tanhf(pv + sel);

        // 4) final output (every thread owns a distinct (batch,row))
        int tt = dir ? (T_ - 1 - t) : t;
        g_hcat[((batch * T_ + tt) << 10) + colbase] = hn;

        if (t < T_ - 1) {
            // 5) publish h_t to buf[t&1] ([batch][row] layout) + pv prefetch
            __stcg(hx + (t & 1) * 2048 + kq * 512 + grow, hn);
            int tn = dir ? (T_ - 2 - t) : (t + 1);
            pv = __ldg(&g_pre[((batch * T_ + tn) << 10) + colbase]);

            // 6) all publishes done -> single release-increment
            __syncthreads();
            if (tid == 0)
                asm volatile("red.release.gpu.global.add.u32 [%0], %1;"
                             :: "l"(Cp), "r"(1u) : "memory");
        }
    }
}

// ---------------------------------------------------------------------------
// 4/6) C[m][n] = sum_k g_hcat[m][k] * Bw[n][k] + bias1[n] (+ bias2[n])
// M=65536, N=1024, K=1024. BM=128, BN=64, BK=16, 256 thr, 8x4 microtile,
// f32x2 packed along M.  (R3 measured-best version, verbatim.)
// ---------------------------------------------------------------------------
__global__ __launch_bounds__(256)
void gemm_k(const float* __restrict__ Bw,
            const float* __restrict__ bias1,
            const float* __restrict__ bias2,
            float* __restrict__ Cext,
            int use_pre)
{
    __shared__ float As[16 * 130];   // [k][m]
    __shared__ float Bs[16 * 68];    // [k][n]

    float* C = use_pre ? g_pre : Cext;
    const int K = 1024;
    int m0 = blockIdx.y * 128;
    int n0 = blockIdx.x * 64;
    int tid = threadIdx.x;
    int tx = tid & 15;               // n-group: cols n0 + tx*4 .. +4
    int ty = tid >> 4;               // m-group: rows m0 + ty*8 .. +8

    unsigned long long acc[4][4];    // [m-pair][n] packed f32x2
#pragma unroll
    for (int i = 0; i < 4; i++)
#pragma unroll
        for (int j = 0; j < 4; j++) acc[i][j] = 0ULL;

    for (int kt = 0; kt < K; kt += 16) {
#pragma unroll
        for (int i = 0; i < 2; i++) {
            int j  = tid + 256 * i;
            int m  = j >> 2, kq = j & 3;
            float4 v = *(const float4*)&g_hcat[(size_t)(m0 + m) * 1024 + kt + kq * 4];
            As[(kq * 4 + 0) * 130 + m] = v.x;
            As[(kq * 4 + 1) * 130 + m] = v.y;
            As[(kq * 4 + 2) * 130 + m] = v.z;
            As[(kq * 4 + 3) * 130 + m] = v.w;
        }
        {
            int n = tid >> 2, kq = tid & 3;
            float4 v = *(const float4*)&Bw[(size_t)(n0 + n) * 1024 + kt + kq * 4];
            Bs[(kq * 4 + 0) * 68 + n] = v.x;
            Bs[(kq * 4 + 1) * 68 + n] = v.y;
            Bs[(kq * 4 + 2) * 68 + n] = v.z;
            Bs[(kq * 4 + 3) * 68 + n] = v.w;
        }
        __syncthreads();

#pragma unroll
        for (int k = 0; k < 16; k++) {
            const unsigned long long* ap =
                (const unsigned long long*)(As + k * 130 + ty * 8);
            unsigned long long a[4];
            a[0] = ap[0]; a[1] = ap[1]; a[2] = ap[2]; a[3] = ap[3];
            float4 bv = *(const float4*)(Bs + k * 68 + tx * 4);
            unsigned long long b[4];
            asm("mov.b64 %0, {%1, %1};" : "=l"(b[0]) : "f"(bv.x));
            asm("mov.b64 %0, {%1, %1};" : "=l"(b[1]) : "f"(bv.y));
            asm("mov.b64 %0, {%1, %1};" : "=l"(b[2]) : "f"(bv.z));
            asm("mov.b64 %0, {%1, %1};" : "=l"(b[3]) : "f"(bv.w));
#pragma unroll
            for (int i = 0; i < 4; i++)
#pragma unroll
                for (int j = 0; j < 4; j++)
                    FMA2(acc[i][j], a[i], b[j]);
        }
        __syncthreads();
    }

    float bs[4];
#pragma unroll
    for (int j = 0; j < 4; j++) {
        int n = n0 + tx * 4 + j;
        bs[j] = bias1[n] + (bias2 ? bias2[n] : 0.0f);
    }
#pragma unroll
    for (int i = 0; i < 4; i++) {
        float lo[4], hi[4];
#pragma unroll
        for (int j = 0; j < 4; j++) {
            float l, h;
            asm("mov.b64 {%0, %1}, %2;" : "=f"(l), "=f"(h) : "l"(acc[i][j]));
            lo[j] = l; hi[j] = h;
        }
        int mA = m0 + ty * 8 + 2 * i;
        float4 r0, r1;
        r0.x = lo[0] + bs[0]; r0.y = lo[1] + bs[1];
        r0.z = lo[2] + bs[2]; r0.w = lo[3] + bs[3];
        r1.x = hi[0] + bs[0]; r1.y = hi[1] + bs[1];
        r1.z = hi[2] + bs[2]; r1.w = hi[3] + bs[3];
        *(float4*)&C[(size_t)mA * 1024 + n0 + tx * 4]       = r0;
        *(float4*)&C[(size_t)(mA + 1) * 1024 + n0 + tx * 4] = r1;
    }
}

// ---------------------------------------------------------------------------
extern "C" void kernel_launch(void* const* d_in, const int* in_sizes, int n_in,
                              void* d_out, int out_size)
{
    const int*   x    = (const int*)  d_in[0];
    const float* Wih0 = (const float*)d_in[1];
    const float* Whh0 = (const float*)d_in[2];
    const float* bih0 = (const float*)d_in[3];
    const float* bhh0 = (const float*)d_in[4];
    const float* Wih1 = (const float*)d_in[5];
    const float* Whh1 = (const float*)d_in[6];
    const float* bih1 = (const float*)d_in[7];
    const float* bhh1 = (const float*)d_in[8];
    const float* fcW  = (const float*)d_in[9];
    const float* fcb  = (const float*)d_in[10];
    float* out = (float*)d_out;

    transpose_k<<<dim3(V_ / 32, H_ / 32, 2), dim3(32, 8)>>>(Wih0);      // #1
    gather_k<<<BT_, 256>>>(x, bih0, bhh0);                              // #2
    dummy_k<<<1, 32>>>();                                               // #3
    rnn_layer_k<<<128, 256>>>(Whh0, 0);                                 // #4 <- ncu
    gemm_k<<<dim3(16, BT_ / 128), 256>>>(Wih1, bih1, bhh1, nullptr, 1); // #5
    rnn_layer_k<<<128, 256>>>(Whh1, 1);                                 // #6
    gemm_k<<<dim3(16, BT_ / 128), 256>>>(fcW, fcb, nullptr, out, 0);    // #7
}